// round 5
// baseline (speedup 1.0000x reference)
#include <cuda_runtime.h>
#include <cstdint>

// SessionSpatialProjector via mma.sync tf32 tensor cores.
// out[b,s,t] = sum_c W[sid[b],s,c] * x[b,c,t] + bias[sid[b],s]; 0 for t >= seq_len[b].
// x [64,128,4096] f32, W [8,256,128] f32, bias [8,256] f32, out [64,256,4096] f32.
// W is staged in SMEM pre-packed into mma fragment layout -> A loads are single LDS.128.

#define BB   64
#define CMAX 128
#define TT   4096
#define SS   256

#define TILE_S 128
#define TILE_T 128
#define XS_STR 136      // x smem row stride (floats): bank = (8k+t)%32, conflict-free
#define XBUF   (32 * XS_STR)

static __device__ __forceinline__ uint32_t f2tf32(float f) {
    uint32_t u; asm("cvt.rna.tf32.f32 %0, %1;" : "=r"(u) : "f"(f)); return u;
}
static __device__ __forceinline__ uint32_t smem_u32(const void* p) {
    uint32_t a;
    asm("{ .reg .u64 t; cvta.to.shared.u64 t, %1; cvt.u32.u64 %0, t; }" : "=r"(a) : "l"(p));
    return a;
}
static __device__ __forceinline__ void cp16(uint32_t dst, const void* src) {
    asm volatile("cp.async.cg.shared.global [%0], [%1], 16;" :: "r"(dst), "l"(src));
}
static __device__ __forceinline__ void mma_tf32(float& d0, float& d1, float& d2, float& d3,
                                                uint32_t a0, uint32_t a1, uint32_t a2, uint32_t a3,
                                                uint32_t b0, uint32_t b1) {
    asm volatile(
        "mma.sync.aligned.m16n8k8.row.col.f32.tf32.tf32.f32 "
        "{%0,%1,%2,%3}, {%4,%5,%6,%7}, {%8,%9}, {%0,%1,%2,%3};"
        : "+f"(d0), "+f"(d1), "+f"(d2), "+f"(d3)
        : "r"(a0), "r"(a1), "r"(a2), "r"(a3), "r"(b0), "r"(b1));
}

__global__ __launch_bounds__(256, 2)
void ssp_mma(const float* __restrict__ x,
             const float* __restrict__ W,
             const float* __restrict__ bias,
             const int*   __restrict__ sid,
             const int*   __restrict__ ccnt,
             const int*   __restrict__ slen_,
             float*       __restrict__ out)
{
    extern __shared__ float sm[];
    float*  biasS = sm;                        // 128 floats
    float4* Af    = (float4*)(sm + 128);       // 8 rb * 16 kb * 32 lanes fragments (64 KB)
    float*  Xs    = sm + 128 + 4096 * 4;       // 2 * XBUF

    const int tid  = threadIdx.x;
    const int lane = tid & 31;
    const int wid  = tid >> 5;
    const int lp   = lane >> 2;   // 0..7
    const int lq   = lane & 3;    // 0..3
    const int wsi  = wid >> 2;    // 0..1  (s)
    const int wti  = wid & 3;     // 0..3  (t)
    const int tb   = wti * 32;

    const int b  = blockIdx.z;
    const int s0 = blockIdx.y * TILE_S;
    const int t0 = blockIdx.x * TILE_T;
    const int sl = slen_[b];

    float* outb = out + ((size_t)b * SS + s0) * TT + t0;

    // Fully masked tile: pure zero fill.
    if (t0 >= sl) {
        #pragma unroll 4
        for (int i = 0; i < 16; i++) {
            int idx = tid + i * 256;            // 0..4095 float4
            int row = idx >> 5, c4 = idx & 31;
            *(float4*)(outb + (size_t)row * TT + c4 * 4) = make_float4(0.f, 0.f, 0.f, 0.f);
        }
        return;
    }

    const int sess = sid[b];
    const int cc   = ccnt[b];
    const int nch  = (cc + 31) >> 5;           // 32-c chunks (2..4)

    const float* xg = x + (size_t)b * CMAX * TT + t0;

    // --- Issue x chunk-0 cp.async FIRST (overlaps with W fragment pack) ---
    {
        #pragma unroll
        for (int i = 0; i < 4; i++) {
            int idx = tid + i * 256;
            int k = idx >> 5, t4 = idx & 31;
            cp16(smem_u32(Xs + k * XS_STR + t4 * 4),
                 xg + (size_t)k * TT + t4 * 4);
        }
        asm volatile("cp.async.commit_group;" ::: "memory");
    }

    if (tid < TILE_S) biasS[tid] = bias[sess * SS + s0 + tid];

    // --- W -> SMEM in mma fragment layout (tf32-rounded). ---
    // Fragment (rb, kb, lane): a0=W[rb*16+lp][kb*8+lq]  a1=+8 row  a2=+4 col  a3=both.
    // 8*16*32 = 4096 fragments; 16 per thread, lane-of-fragment == thread lane.
    {
        const float* Wg = W + ((size_t)sess * SS + s0) * CMAX;
        const float* wr = Wg + (size_t)lp * CMAX + lq;     // rb/kb offsets added below
        #pragma unroll
        for (int i = 0; i < 16; i++) {
            int fk = wid + i * 8;          // 0..127
            int kb = fk & 15;
            int rb = fk >> 4;
            const float* p = wr + (size_t)rb * 16 * CMAX + kb * 8;
            float4 v;
            v.x = __uint_as_float(f2tf32(p[0]));
            v.y = __uint_as_float(f2tf32(p[8 * CMAX]));
            v.z = __uint_as_float(f2tf32(p[4]));
            v.w = __uint_as_float(f2tf32(p[8 * CMAX + 4]));
            Af[(rb * 16 + kb) * 32 + lane] = v;
        }
    }

    float acc[4][4][4];
    #pragma unroll
    for (int mt = 0; mt < 4; mt++)
        #pragma unroll
        for (int nt = 0; nt < 4; nt++)
            #pragma unroll
            for (int r = 0; r < 4; r++)
                acc[mt][nt][r] = 0.f;

    const float4* AfW = Af + (wsi * 4) * 16 * 32 + lane;   // rb = wsi*4 + mt

    for (int q = 0; q < nch; q++) {
        if (q + 1 < nch) {
            float* dstb = Xs + ((q + 1) & 1) * XBUF;
            #pragma unroll
            for (int i = 0; i < 4; i++) {
                int idx = tid + i * 256;
                int k = idx >> 5, t4 = idx & 31;
                cp16(smem_u32(dstb + k * XS_STR + t4 * 4),
                     xg + (size_t)((q + 1) * 32 + k) * TT + t4 * 4);
            }
            asm volatile("cp.async.commit_group;" ::: "memory");
            asm volatile("cp.async.wait_group 1;" ::: "memory");
        } else {
            asm volatile("cp.async.wait_group 0;" ::: "memory");
        }
        __syncthreads();   // covers: W pack (q==0), cp.async arrival, prev-iter LDS done

        const float* Xb = Xs + (q & 1) * XBUF;

        #pragma unroll
        for (int k8 = 0; k8 < 4; k8++) {
            const int kb = q * 4 + k8;

            // A fragments: one LDS.128 each, conflict-free (contiguous 512B per warp)
            float4 a[4];
            #pragma unroll
            for (int mt = 0; mt < 4; mt++)
                a[mt] = AfW[(mt * 16 + kb) * 32];

            // B fragments from x smem (k x t), conflict-free scalar LDS + rna round
            uint32_t B0[4], B1[4];
            const float* xr0 = Xb + (k8 * 8 + lq) * XS_STR + tb + lp;
            const float* xr1 = xr0 + 4 * XS_STR;
            #pragma unroll
            for (int nt = 0; nt < 4; nt++) {
                B0[nt] = f2tf32(xr0[nt * 8]);
                B1[nt] = f2tf32(xr1[nt * 8]);
            }

            #pragma unroll
            for (int mt = 0; mt < 4; mt++) {
                uint32_t a0 = __float_as_uint(a[mt].x);
                uint32_t a1 = __float_as_uint(a[mt].y);
                uint32_t a2 = __float_as_uint(a[mt].z);
                uint32_t a3 = __float_as_uint(a[mt].w);
                #pragma unroll
                for (int nt = 0; nt < 4; nt++)
                    mma_tf32(acc[mt][nt][0], acc[mt][nt][1], acc[mt][nt][2], acc[mt][nt][3],
                             a0, a1, a2, a3, B0[nt], B1[nt]);
            }
        }
        __syncthreads();
    }

    // --- Epilogue: bias + seq mask, float2 stores along t ---
    #pragma unroll
    for (int mt = 0; mt < 4; mt++) {
        int sr = wsi * 64 + mt * 16 + lp;
        float bs0 = biasS[sr];
        float bs1 = biasS[sr + 8];
        float* o0 = outb + (size_t)sr * TT;
        float* o1 = o0 + (size_t)8 * TT;
        #pragma unroll
        for (int nt = 0; nt < 4; nt++) {
            int tc = tb + nt * 8 + lq * 2;      // even -> 8B aligned
            bool m0 = (t0 + tc)     < sl;
            bool m1 = (t0 + tc + 1) < sl;
            float2 v0, v1;
            v0.x = m0 ? acc[mt][nt][0] + bs0 : 0.f;
            v0.y = m1 ? acc[mt][nt][1] + bs0 : 0.f;
            v1.x = m0 ? acc[mt][nt][2] + bs1 : 0.f;
            v1.y = m1 ? acc[mt][nt][3] + bs1 : 0.f;
            *(float2*)(o0 + tc) = v0;
            *(float2*)(o1 + tc) = v1;
        }
    }
}

extern "C" void kernel_launch(void* const* d_in, const int* in_sizes, int n_in,
                              void* d_out, int out_size)
{
    const float* x      = (const float*)d_in[0];
    const float* W      = (const float*)d_in[1];
    const float* bias   = (const float*)d_in[2];
    const int*   sid    = (const int*)d_in[3];
    const int*   ccount = (const int*)d_in[4];
    const int*   slen   = (const int*)d_in[5];
    float* out = (float*)d_out;

    const int smem_bytes = (128 + 4096 * 4 + 2 * XBUF) * 4;   // ~98.5 KB
    cudaFuncSetAttribute(ssp_mma, cudaFuncAttributeMaxDynamicSharedMemorySize, smem_bytes);

    dim3 grid(TT / TILE_T, SS / TILE_S, BB);   // (32, 2, 64)
    ssp_mma<<<grid, 256, smem_bytes>>>(x, W, bias, sid, ccount, slen, out);
}

// round 7
// speedup vs baseline: 1.1897x; 1.1897x over previous
#include <cuda_runtime.h>
#include <cstdint>

// SessionSpatialProjector via mma.sync tf32 tensor cores.
// out[b,s,t] = sum_c W[sid[b],s,c] * x[b,c,t] + bias[sid[b],s]; 0 for t >= seq_len[b].
// x [64,128,4096] f32, W [8,256,128] f32, bias [8,256] f32, out [64,256,4096] f32.
// R7 (= R6 resubmit after infra failure): 64x128 CTA tile, 32 accums/thread, 3 CTAs/SM.

#define BB   64
#define CMAX 128
#define TT   4096
#define SS   256

#define TILE_S 64
#define TILE_T 128
#define WS_STR 132      // W smem row stride (floats): A-frag bank = (4*lp+lq)%32, conflict-free
#define XS_STR 136      // x smem row stride (floats): B-frag bank = (8*lq+lp)%32, conflict-free
#define XBUF   (32 * XS_STR)

static __device__ __forceinline__ uint32_t f2tf32(float f) {
    uint32_t u; asm("cvt.rna.tf32.f32 %0, %1;" : "=r"(u) : "f"(f)); return u;
}
static __device__ __forceinline__ uint32_t smem_u32(const void* p) {
    uint32_t a;
    asm("{ .reg .u64 t; cvta.to.shared.u64 t, %1; cvt.u32.u64 %0, t; }" : "=r"(a) : "l"(p));
    return a;
}
static __device__ __forceinline__ void cp16(uint32_t dst, const void* src) {
    asm volatile("cp.async.cg.shared.global [%0], [%1], 16;" :: "r"(dst), "l"(src));
}
static __device__ __forceinline__ void mma_tf32(float& d0, float& d1, float& d2, float& d3,
                                                uint32_t a0, uint32_t a1, uint32_t a2, uint32_t a3,
                                                uint32_t b0, uint32_t b1) {
    asm volatile(
        "mma.sync.aligned.m16n8k8.row.col.f32.tf32.tf32.f32 "
        "{%0,%1,%2,%3}, {%4,%5,%6,%7}, {%8,%9}, {%0,%1,%2,%3};"
        : "+f"(d0), "+f"(d1), "+f"(d2), "+f"(d3)
        : "r"(a0), "r"(a1), "r"(a2), "r"(a3), "r"(b0), "r"(b1));
}

__global__ __launch_bounds__(256, 3)
void ssp_mma(const float* __restrict__ x,
             const float* __restrict__ W,
             const float* __restrict__ bias,
             const int*   __restrict__ sid,
             const int*   __restrict__ ccnt,
             const int*   __restrict__ slen_,
             float*       __restrict__ out)
{
    extern __shared__ float sm[];
    float* biasS = sm;                          // 64 floats
    float* Ws    = sm + 64;                     // 64 * WS_STR
    float* Xs    = Ws + TILE_S * WS_STR;        // 2 * XBUF

    const int tid  = threadIdx.x;
    const int lane = tid & 31;
    const int wid  = tid >> 5;
    const int lp   = lane >> 2;   // 0..7
    const int lq   = lane & 3;    // 0..3
    const int wsi  = wid >> 2;    // 0..1  (s)   warp tile 32s x 32t
    const int wti  = wid & 3;     // 0..3  (t)
    const int sb   = wsi * 32;
    const int tb   = wti * 32;

    const int b  = blockIdx.z;
    const int s0 = blockIdx.y * TILE_S;
    const int t0 = blockIdx.x * TILE_T;
    const int sl = slen_[b];

    float* outb = out + ((size_t)b * SS + s0) * TT + t0;

    // Fully masked tile: pure zero fill (64 x 128 floats = 2048 float4, 8/thread).
    if (t0 >= sl) {
        #pragma unroll 4
        for (int i = 0; i < 8; i++) {
            int idx = tid + i * 256;
            int row = idx >> 5, c4 = idx & 31;
            *(float4*)(outb + (size_t)row * TT + c4 * 4) = make_float4(0.f, 0.f, 0.f, 0.f);
        }
        return;
    }

    const int sess = sid[b];
    const int cc   = ccnt[b];
    const int nch  = (cc + 31) >> 5;            // 32-c chunks (2..4)

    const float* xg = x + (size_t)b * CMAX * TT + t0;

    // --- x chunk-0 cp.async first (overlaps the W stage) ---
    {
        #pragma unroll
        for (int i = 0; i < 4; i++) {
            int idx = tid + i * 256;
            int k = idx >> 5, t4 = idx & 31;
            cp16(smem_u32(Xs + k * XS_STR + t4 * 4),
                 xg + (size_t)k * TT + t4 * 4);
        }
        asm volatile("cp.async.commit_group;" ::: "memory");
    }

    if (tid < TILE_S) biasS[tid] = bias[sess * SS + s0 + tid];

    // --- W tile -> SMEM (tf32-rounded), coalesced float4. 64x128 = 2048 float4. ---
    {
        const float* Wg = W + ((size_t)sess * SS + s0) * CMAX;
        #pragma unroll
        for (int i = 0; i < 8; i++) {
            int idx = tid + i * 256;
            int row = idx >> 5, c4 = idx & 31;
            float4 w4 = *(const float4*)(Wg + (size_t)row * CMAX + c4 * 4);
            float* d = Ws + row * WS_STR + c4 * 4;
            d[0] = __uint_as_float(f2tf32(w4.x));
            d[1] = __uint_as_float(f2tf32(w4.y));
            d[2] = __uint_as_float(f2tf32(w4.z));
            d[3] = __uint_as_float(f2tf32(w4.w));
        }
    }

    float acc[2][4][4];
    #pragma unroll
    for (int mt = 0; mt < 2; mt++)
        #pragma unroll
        for (int nt = 0; nt < 4; nt++)
            #pragma unroll
            for (int r = 0; r < 4; r++)
                acc[mt][nt][r] = 0.f;

    for (int q = 0; q < nch; q++) {
        if (q + 1 < nch) {
            float* dstb = Xs + ((q + 1) & 1) * XBUF;
            #pragma unroll
            for (int i = 0; i < 4; i++) {
                int idx = tid + i * 256;
                int k = idx >> 5, t4 = idx & 31;
                cp16(smem_u32(dstb + k * XS_STR + t4 * 4),
                     xg + (size_t)((q + 1) * 32 + k) * TT + t4 * 4);
            }
            asm volatile("cp.async.commit_group;" ::: "memory");
            asm volatile("cp.async.wait_group 1;" ::: "memory");
        } else {
            asm volatile("cp.async.wait_group 0;" ::: "memory");
        }
        __syncthreads();   // covers W stage (q==0), cp.async arrival, prev-iter LDS done

        const float* Xb = Xs + (q & 1) * XBUF;
        const int kk0 = q * 32;

        #pragma unroll
        for (int k0 = 0; k0 < 32; k0 += 8) {
            // B fragments (x, k x t col-major), tf32-rounded at load
            uint32_t B0[4], B1[4];
            const float* xr0 = Xb + (k0 + lq) * XS_STR + tb + lp;
            const float* xr1 = xr0 + 4 * XS_STR;
            #pragma unroll
            for (int nt = 0; nt < 4; nt++) {
                B0[nt] = f2tf32(xr0[nt * 8]);
                B1[nt] = f2tf32(xr1[nt * 8]);
            }
            #pragma unroll
            for (int mt = 0; mt < 2; mt++) {
                const float* wr0 = Ws + (sb + mt * 16 + lp) * WS_STR + kk0 + k0 + lq;
                const float* wr1 = wr0 + 8 * WS_STR;
                uint32_t a0 = __float_as_uint(wr0[0]);
                uint32_t a1 = __float_as_uint(wr1[0]);
                uint32_t a2 = __float_as_uint(wr0[4]);
                uint32_t a3 = __float_as_uint(wr1[4]);
                #pragma unroll
                for (int nt = 0; nt < 4; nt++)
                    mma_tf32(acc[mt][nt][0], acc[mt][nt][1], acc[mt][nt][2], acc[mt][nt][3],
                             a0, a1, a2, a3, B0[nt], B1[nt]);
            }
        }
        __syncthreads();
    }

    // --- Epilogue: bias + seq mask, float2 stores along t ---
    #pragma unroll
    for (int mt = 0; mt < 2; mt++) {
        int sr = sb + mt * 16 + lp;
        float bs0 = biasS[sr];
        float bs1 = biasS[sr + 8];
        float* o0 = outb + (size_t)sr * TT;
        float* o1 = o0 + (size_t)8 * TT;
        #pragma unroll
        for (int nt = 0; nt < 4; nt++) {
            int tc = tb + nt * 8 + lq * 2;      // even -> 8B aligned
            bool m0 = (t0 + tc)     < sl;
            bool m1 = (t0 + tc + 1) < sl;
            float2 v0, v1;
            v0.x = m0 ? acc[mt][nt][0] + bs0 : 0.f;
            v0.y = m1 ? acc[mt][nt][1] + bs0 : 0.f;
            v1.x = m0 ? acc[mt][nt][2] + bs1 : 0.f;
            v1.y = m1 ? acc[mt][nt][3] + bs1 : 0.f;
            *(float2*)(o0 + tc) = v0;
            *(float2*)(o1 + tc) = v1;
        }
    }
}

extern "C" void kernel_launch(void* const* d_in, const int* in_sizes, int n_in,
                              void* d_out, int out_size)
{
    const float* x      = (const float*)d_in[0];
    const float* W      = (const float*)d_in[1];
    const float* bias   = (const float*)d_in[2];
    const int*   sid    = (const int*)d_in[3];
    const int*   ccount = (const int*)d_in[4];
    const int*   slen   = (const int*)d_in[5];
    float* out = (float*)d_out;

    const int smem_bytes = (64 + TILE_S * WS_STR + 2 * XBUF) * 4;   // ~67.3 KB
    cudaFuncSetAttribute(ssp_mma, cudaFuncAttributeMaxDynamicSharedMemorySize, smem_bytes);

    dim3 grid(TT / TILE_T, SS / TILE_S, BB);   // (32, 4, 64)
    ssp_mma<<<grid, 256, smem_bytes>>>(x, W, bias, sid, ccount, slen, out);
}

// round 9
// speedup vs baseline: 1.2547x; 1.0546x over previous
#include <cuda_runtime.h>
#include <cstdint>

// SessionSpatialProjector via mma.sync tf32 tensor cores.
// out[b,s,t] = sum_c W[sid[b],s,c] * x[b,c,t] + bias[sid[b],s]; 0 for t >= seq_len[b].
// x [64,128,4096] f32, W [8,256,128] f32, bias [8,256] f32, out [64,256,4096] f32.
// R9 (= R8 resubmit after infra failure): 128x128 tile + W staged in mma-fragment layout
// via coalesced LDG -> STS scatter. A-operand loads become single LDS.128 per 16x16 block.

#define BB   64
#define CMAX 128
#define TT   4096
#define SS   256

#define TILE_S 128
#define TILE_T 128
#define FRAG_STR 132    // words per fragment unit (33 float4): STS 2-way max, LDS.128 conflict-free
#define XS_STR 136      // x smem row stride (floats): B-frag bank = (8*lq+lp)%32, conflict-free
#define XBUF   (32 * XS_STR)

static __device__ __forceinline__ uint32_t f2tf32(float f) {
    uint32_t u; asm("cvt.rna.tf32.f32 %0, %1;" : "=r"(u) : "f"(f)); return u;
}
static __device__ __forceinline__ uint32_t smem_u32(const void* p) {
    uint32_t a;
    asm("{ .reg .u64 t; cvta.to.shared.u64 t, %1; cvt.u32.u64 %0, t; }" : "=r"(a) : "l"(p));
    return a;
}
static __device__ __forceinline__ void cp16(uint32_t dst, const void* src) {
    asm volatile("cp.async.cg.shared.global [%0], [%1], 16;" :: "r"(dst), "l"(src));
}
static __device__ __forceinline__ void mma_tf32(float& d0, float& d1, float& d2, float& d3,
                                                uint32_t a0, uint32_t a1, uint32_t a2, uint32_t a3,
                                                uint32_t b0, uint32_t b1) {
    asm volatile(
        "mma.sync.aligned.m16n8k8.row.col.f32.tf32.tf32.f32 "
        "{%0,%1,%2,%3}, {%4,%5,%6,%7}, {%8,%9}, {%0,%1,%2,%3};"
        : "+f"(d0), "+f"(d1), "+f"(d2), "+f"(d3)
        : "r"(a0), "r"(a1), "r"(a2), "r"(a3), "r"(b0), "r"(b1));
}

__global__ __launch_bounds__(256, 2)
void ssp_mma(const float* __restrict__ x,
             const float* __restrict__ W,
             const float* __restrict__ bias,
             const int*   __restrict__ sid,
             const int*   __restrict__ ccnt,
             const int*   __restrict__ slen_,
             float*       __restrict__ out)
{
    extern __shared__ float sm[];
    float* biasS = sm;                          // 128 floats (512B, keeps Af 16B-aligned)
    float* AfF   = sm + 128;                    // 128 frags * FRAG_STR words (~67.6 KB)
    float* Xs    = AfF + 128 * FRAG_STR;        // 2 * XBUF

    const int tid  = threadIdx.x;
    const int lane = tid & 31;
    const int wid  = tid >> 5;
    const int lp   = lane >> 2;   // 0..7
    const int lq   = lane & 3;    // 0..3
    const int wsi  = wid >> 2;    // 0..1  (s)  warp tile 64s x 32t
    const int wti  = wid & 3;     // 0..3  (t)
    const int tb   = wti * 32;

    const int b  = blockIdx.z;
    const int s0 = blockIdx.y * TILE_S;
    const int t0 = blockIdx.x * TILE_T;
    const int sl = slen_[b];

    float* outb = out + ((size_t)b * SS + s0) * TT + t0;

    // Fully masked tile: pure zero fill.
    if (t0 >= sl) {
        #pragma unroll 4
        for (int i = 0; i < 16; i++) {
            int idx = tid + i * 256;            // 0..4095 float4
            int row = idx >> 5, c4 = idx & 31;
            *(float4*)(outb + (size_t)row * TT + c4 * 4) = make_float4(0.f, 0.f, 0.f, 0.f);
        }
        return;
    }

    const int sess = sid[b];
    const int cc   = ccnt[b];
    const int nch  = (cc + 31) >> 5;           // 32-c chunks (2..4)

    const float* xg = x + (size_t)b * CMAX * TT + t0;

    // --- x chunk-0 cp.async first (overlaps the W stage) ---
    {
        #pragma unroll
        for (int i = 0; i < 4; i++) {
            int idx = tid + i * 256;
            int k = idx >> 5, t4 = idx & 31;
            cp16(smem_u32(Xs + k * XS_STR + t4 * 4),
                 xg + (size_t)k * TT + t4 * 4);
        }
        asm volatile("cp.async.commit_group;" ::: "memory");
    }

    if (tid < TILE_S) biasS[tid] = bias[sess * SS + s0 + tid];

    // --- W tile -> SMEM in mma fragment layout (tf32-rounded). ---
    // Coalesced float4 LDG, then 4 scattered STS.32 into fragment positions:
    //   element W[row][c] -> frag f=(row>>4)*16+(c>>3), lane=(row&7)*4+(c&3),
    //   component = (row>>3) + 2*((c>>2)&1)   {a0,a1,a2,a3} packing.
    {
        const float* Wg = W + ((size_t)sess * SS + s0) * CMAX;
        #pragma unroll
        for (int i = 0; i < 16; i++) {
            int idx = tid + i * 256;
            int row = idx >> 5, c4 = idx & 31;       // holds W[row][4c4..4c4+3]
            float4 w4 = *(const float4*)(Wg + (size_t)row * CMAX + c4 * 4);
            int rb = row >> 4, r = row & 15;
            int f  = (rb << 4) + (c4 >> 1);
            float* d = AfF + f * FRAG_STR + ((r & 7) << 4) + ((c4 & 1) << 1) + (r >> 3);
            d[0]  = __uint_as_float(f2tf32(w4.x));   // c&3 = 0 -> word + 0
            d[4]  = __uint_as_float(f2tf32(w4.y));   // c&3 = 1 -> word + 4
            d[8]  = __uint_as_float(f2tf32(w4.z));
            d[12] = __uint_as_float(f2tf32(w4.w));
        }
    }

    float acc[4][4][4];
    #pragma unroll
    for (int mt = 0; mt < 4; mt++)
        #pragma unroll
        for (int nt = 0; nt < 4; nt++)
            #pragma unroll
            for (int r = 0; r < 4; r++)
                acc[mt][nt][r] = 0.f;

    // This warp's fragment base: rb = wsi*4 + mt, frag = rb*16 + kb
    const float* AfW = AfF + (wsi * 4) * 16 * FRAG_STR + lane * 4;

    for (int q = 0; q < nch; q++) {
        if (q + 1 < nch) {
            float* dstb = Xs + ((q + 1) & 1) * XBUF;
            #pragma unroll
            for (int i = 0; i < 4; i++) {
                int idx = tid + i * 256;
                int k = idx >> 5, t4 = idx & 31;
                cp16(smem_u32(dstb + k * XS_STR + t4 * 4),
                     xg + (size_t)((q + 1) * 32 + k) * TT + t4 * 4);
            }
            asm volatile("cp.async.commit_group;" ::: "memory");
            asm volatile("cp.async.wait_group 1;" ::: "memory");
        } else {
            asm volatile("cp.async.wait_group 0;" ::: "memory");
        }
        __syncthreads();   // covers W pack (q==0), cp.async arrival, prev-iter LDS done

        const float* Xb = Xs + (q & 1) * XBUF;

        #pragma unroll
        for (int k8 = 0; k8 < 4; k8++) {
            const int kb = q * 4 + k8;

            // A fragments: one LDS.128 per 16x16 block, conflict-free
            float4 a[4];
            #pragma unroll
            for (int mt = 0; mt < 4; mt++)
                a[mt] = *(const float4*)(AfW + (mt * 16 + kb) * FRAG_STR);

            // B fragments from x smem (k x t), conflict-free scalar LDS + rna round
            uint32_t B0[4], B1[4];
            const float* xr0 = Xb + (k8 * 8 + lq) * XS_STR + tb + lp;
            const float* xr1 = xr0 + 4 * XS_STR;
            #pragma unroll
            for (int nt = 0; nt < 4; nt++) {
                B0[nt] = f2tf32(xr0[nt * 8]);
                B1[nt] = f2tf32(xr1[nt * 8]);
            }

            #pragma unroll
            for (int mt = 0; mt < 4; mt++) {
                uint32_t a0 = __float_as_uint(a[mt].x);
                uint32_t a1 = __float_as_uint(a[mt].y);
                uint32_t a2 = __float_as_uint(a[mt].z);
                uint32_t a3 = __float_as_uint(a[mt].w);
                #pragma unroll
                for (int nt = 0; nt < 4; nt++)
                    mma_tf32(acc[mt][nt][0], acc[mt][nt][1], acc[mt][nt][2], acc[mt][nt][3],
                             a0, a1, a2, a3, B0[nt], B1[nt]);
            }
        }
        __syncthreads();
    }

    // --- Epilogue: bias + seq mask, float2 stores along t ---
    #pragma unroll
    for (int mt = 0; mt < 4; mt++) {
        int sr = wsi * 64 + mt * 16 + lp;
        float bs0 = biasS[sr];
        float bs1 = biasS[sr + 8];
        float* o0 = outb + (size_t)sr * TT;
        float* o1 = o0 + (size_t)8 * TT;
        #pragma unroll
        for (int nt = 0; nt < 4; nt++) {
            int tc = tb + nt * 8 + lq * 2;      // even -> 8B aligned
            bool m0 = (t0 + tc)     < sl;
            bool m1 = (t0 + tc + 1) < sl;
            float2 v0, v1;
            v0.x = m0 ? acc[mt][nt][0] + bs0 : 0.f;
            v0.y = m1 ? acc[mt][nt][1] + bs0 : 0.f;
            v1.x = m0 ? acc[mt][nt][2] + bs1 : 0.f;
            v1.y = m1 ? acc[mt][nt][3] + bs1 : 0.f;
            *(float2*)(o0 + tc) = v0;
            *(float2*)(o1 + tc) = v1;
        }
    }
}

extern "C" void kernel_launch(void* const* d_in, const int* in_sizes, int n_in,
                              void* d_out, int out_size)
{
    const float* x      = (const float*)d_in[0];
    const float* W      = (const float*)d_in[1];
    const float* bias   = (const float*)d_in[2];
    const int*   sid    = (const int*)d_in[3];
    const int*   ccount = (const int*)d_in[4];
    const int*   slen   = (const int*)d_in[5];
    float* out = (float*)d_out;

    const int smem_bytes = (128 + 128 * FRAG_STR + 2 * XBUF) * 4;   // ~101 KB
    cudaFuncSetAttribute(ssp_mma, cudaFuncAttributeMaxDynamicSharedMemorySize, smem_bytes);

    dim3 grid(TT / TILE_T, SS / TILE_S, BB);   // (32, 2, 64)
    ssp_mma<<<grid, 256, smem_bytes>>>(x, W, bias, sid, ccount, slen, out);
}

// round 10
// speedup vs baseline: 1.3405x; 1.0684x over previous
#include <cuda_runtime.h>
#include <cstdint>

// SessionSpatialProjector via mma.sync tf32 tensor cores.
// out[b,s,t] = sum_c W[sid[b],s,c] * x[b,c,t] + bias[sid[b],s]; 0 for t >= seq_len[b].
// x [64,128,4096] f32, W [8,256,128] f32, bias [8,256] f32, out [64,256,4096] f32.
// R10: R3 inner loop + 2 t-subtiles per CTA. W prologue amortized 2x; cp.async ring runs
// across the subtile boundary so the epilogue overlaps the next subtile's global loads.

#define BB   64
#define CMAX 128
#define TT   4096
#define SS   256

#define TILE_S 128
#define TILE_T 128
#define NSUB   2
#define WS_STR 132      // W smem row stride (floats): A-frag bank = conflict-free
#define XS_STR 136      // x smem row stride (floats): B-frag bank = conflict-free
#define XBUF   (32 * XS_STR)

static __device__ __forceinline__ uint32_t f2tf32(float f) {
    uint32_t u; asm("cvt.rna.tf32.f32 %0, %1;" : "=r"(u) : "f"(f)); return u;
}
static __device__ __forceinline__ uint32_t smem_u32(const void* p) {
    uint32_t a;
    asm("{ .reg .u64 t; cvta.to.shared.u64 t, %1; cvt.u32.u64 %0, t; }" : "=r"(a) : "l"(p));
    return a;
}
static __device__ __forceinline__ void cp16(uint32_t dst, const void* src) {
    asm volatile("cp.async.cg.shared.global [%0], [%1], 16;" :: "r"(dst), "l"(src));
}
static __device__ __forceinline__ void mma_tf32(float& d0, float& d1, float& d2, float& d3,
                                                uint32_t a0, uint32_t a1, uint32_t a2, uint32_t a3,
                                                uint32_t b0, uint32_t b1) {
    asm volatile(
        "mma.sync.aligned.m16n8k8.row.col.f32.tf32.tf32.f32 "
        "{%0,%1,%2,%3}, {%4,%5,%6,%7}, {%8,%9}, {%0,%1,%2,%3};"
        : "+f"(d0), "+f"(d1), "+f"(d2), "+f"(d3)
        : "r"(a0), "r"(a1), "r"(a2), "r"(a3), "r"(b0), "r"(b1));
}

__global__ __launch_bounds__(256, 2)
void ssp_mma(const float* __restrict__ x,
             const float* __restrict__ W,
             const float* __restrict__ bias,
             const int*   __restrict__ sid,
             const int*   __restrict__ ccnt,
             const int*   __restrict__ slen_,
             float*       __restrict__ out)
{
    extern __shared__ float sm[];
    float* biasS = sm;                         // 128 floats
    float* Ws    = sm + 128;                   // 128 * WS_STR
    float* Xs    = Ws + TILE_S * WS_STR;       // 2 * XBUF

    const int tid  = threadIdx.x;
    const int lane = tid & 31;
    const int wid  = tid >> 5;
    const int lp   = lane >> 2;   // 0..7
    const int lq   = lane & 3;    // 0..3
    const int wsi  = wid >> 2;    // 0..1  (s)
    const int wti  = wid & 3;     // 0..3  (t)
    const int sb   = wsi * 64;
    const int tb   = wti * 32;

    const int b      = blockIdx.z;
    const int s0     = blockIdx.y * TILE_S;
    const int t_base = blockIdx.x * (TILE_T * NSUB);
    const int sl     = slen_[b];

    // Whole CTA masked: zero-fill both subtiles and exit.
    if (t_base >= sl) {
        float* ob = out + ((size_t)b * SS + s0) * TT + t_base;
        #pragma unroll 4
        for (int i = 0; i < 32; i++) {
            int idx = tid + i * 256;                 // 128 rows * 64 float4
            int row = idx >> 6, c4 = idx & 63;
            *(float4*)(ob + (size_t)row * TT + c4 * 4) = make_float4(0.f, 0.f, 0.f, 0.f);
        }
        return;
    }

    const int sess = sid[b];
    const int cc   = ccnt[b];
    const int nch  = (cc + 31) >> 5;           // 32-c chunks (2..4)

    const float* xg0 = x + (size_t)b * CMAX * TT;

    // --- Prefetch subtile-0 chunk-0 (overlaps the W stage) ---
    {
        const float* xg = xg0 + t_base;
        #pragma unroll
        for (int i = 0; i < 4; i++) {
            int idx = tid + i * 256;
            int k = idx >> 5, t4 = idx & 31;
            cp16(smem_u32(Xs + k * XS_STR + t4 * 4), xg + (size_t)k * TT + t4 * 4);
        }
        asm volatile("cp.async.commit_group;" ::: "memory");
    }

    if (tid < TILE_S) biasS[tid] = bias[sess * SS + s0 + tid];

    // --- W tile -> SMEM (tf32-rounded), coalesced float4. Loaded ONCE per CTA. ---
    {
        const float* Wg = W + ((size_t)sess * SS + s0) * CMAX;
        #pragma unroll
        for (int i = 0; i < 16; i++) {
            int idx = tid + i * 256;
            int row = idx >> 5, c4 = idx & 31;
            float4 w4 = *(const float4*)(Wg + (size_t)row * CMAX + c4 * 4);
            float* d = Ws + row * WS_STR + c4 * 4;
            d[0] = __uint_as_float(f2tf32(w4.x));
            d[1] = __uint_as_float(f2tf32(w4.y));
            d[2] = __uint_as_float(f2tf32(w4.z));
            d[3] = __uint_as_float(f2tf32(w4.w));
        }
    }

    int buf = 0;   // parity of the buffer holding the next chunk to CONSUME

    for (int st = 0; st < NSUB; st++) {
        const int t0 = t_base + st * TILE_T;
        float* outb = out + ((size_t)b * SS + s0) * TT + t0;

        if (t0 >= sl) {
            // masked subtile: zero fill (no x loads were issued for it)
            #pragma unroll 4
            for (int i = 0; i < 16; i++) {
                int idx = tid + i * 256;
                int row = idx >> 5, c4 = idx & 31;
                *(float4*)(outb + (size_t)row * TT + c4 * 4) = make_float4(0.f, 0.f, 0.f, 0.f);
            }
            continue;
        }

        const float* xg = xg0 + t0;

        float acc[4][4][4];
        #pragma unroll
        for (int mt = 0; mt < 4; mt++)
            #pragma unroll
            for (int nt = 0; nt < 4; nt++)
                #pragma unroll
                for (int r = 0; r < 4; r++)
                    acc[mt][nt][r] = 0.f;

        for (int q = 0; q < nch; q++) {
            // Prefetch: next chunk of this subtile, or chunk-0 of the next live subtile.
            bool pre = false;
            const float* psrc = nullptr;
            if (q + 1 < nch) {
                pre = true;  psrc = xg + (size_t)(q + 1) * 32 * TT;
            } else if (st + 1 < NSUB && t0 + TILE_T < sl) {
                pre = true;  psrc = xg + TILE_T;          // next subtile, chunk 0
            }
            if (pre) {
                float* dstb = Xs + (buf ^ 1) * XBUF;
                #pragma unroll
                for (int i = 0; i < 4; i++) {
                    int idx = tid + i * 256;
                    int k = idx >> 5, t4 = idx & 31;
                    cp16(smem_u32(dstb + k * XS_STR + t4 * 4), psrc + (size_t)k * TT + t4 * 4);
                }
                asm volatile("cp.async.commit_group;" ::: "memory");
                asm volatile("cp.async.wait_group 1;" ::: "memory");
            } else {
                asm volatile("cp.async.wait_group 0;" ::: "memory");
            }
            __syncthreads();   // chunk `buf` visible to all; prev buffer free for the prefetch

            const float* Xb = Xs + buf * XBUF;
            const int kk0 = q * 32;

            #pragma unroll
            for (int k0 = 0; k0 < 32; k0 += 8) {
                uint32_t B0[4], B1[4];
                const float* xr0 = Xb + (k0 + lq) * XS_STR + tb + lp;
                const float* xr1 = xr0 + 4 * XS_STR;
                #pragma unroll
                for (int nt = 0; nt < 4; nt++) {
                    B0[nt] = f2tf32(xr0[nt * 8]);
                    B1[nt] = f2tf32(xr1[nt * 8]);
                }
                #pragma unroll
                for (int mt = 0; mt < 4; mt++) {
                    const float* wr0 = Ws + (sb + mt * 16 + lp) * WS_STR + kk0 + k0 + lq;
                    const float* wr1 = wr0 + 8 * WS_STR;
                    uint32_t a0 = __float_as_uint(wr0[0]);
                    uint32_t a1 = __float_as_uint(wr1[0]);
                    uint32_t a2 = __float_as_uint(wr0[4]);
                    uint32_t a3 = __float_as_uint(wr1[4]);
                    #pragma unroll
                    for (int nt = 0; nt < 4; nt++)
                        mma_tf32(acc[mt][nt][0], acc[mt][nt][1], acc[mt][nt][2], acc[mt][nt][3],
                                 a0, a1, a2, a3, B0[nt], B1[nt]);
                }
            }
            buf ^= 1;
            __syncthreads();   // all reads of old buffer done before next iter overwrites it
        }

        // --- Epilogue: bias + seq mask, float2 stores; overlaps in-flight next-subtile loads ---
        #pragma unroll
        for (int mt = 0; mt < 4; mt++) {
            int sr = sb + mt * 16 + lp;
            float bs0 = biasS[sr];
            float bs1 = biasS[sr + 8];
            float* o0 = outb + (size_t)sr * TT;
            float* o1 = o0 + (size_t)8 * TT;
            #pragma unroll
            for (int nt = 0; nt < 4; nt++) {
                int tc = tb + nt * 8 + lq * 2;      // even -> 8B aligned
                bool m0 = (t0 + tc)     < sl;
                bool m1 = (t0 + tc + 1) < sl;
                float2 v0, v1;
                v0.x = m0 ? acc[mt][nt][0] + bs0 : 0.f;
                v0.y = m1 ? acc[mt][nt][1] + bs0 : 0.f;
                v1.x = m0 ? acc[mt][nt][2] + bs1 : 0.f;
                v1.y = m1 ? acc[mt][nt][3] + bs1 : 0.f;
                *(float2*)(o0 + tc) = v0;
                *(float2*)(o1 + tc) = v1;
            }
        }
    }
}

extern "C" void kernel_launch(void* const* d_in, const int* in_sizes, int n_in,
                              void* d_out, int out_size)
{
    const float* x      = (const float*)d_in[0];
    const float* W      = (const float*)d_in[1];
    const float* bias   = (const float*)d_in[2];
    const int*   sid    = (const int*)d_in[3];
    const int*   ccount = (const int*)d_in[4];
    const int*   slen   = (const int*)d_in[5];
    float* out = (float*)d_out;

    const int smem_bytes = (128 + TILE_S * WS_STR + 2 * XBUF) * 4;   // ~103 KB
    cudaFuncSetAttribute(ssp_mma, cudaFuncAttributeMaxDynamicSharedMemorySize, smem_bytes);

    dim3 grid(TT / (TILE_T * NSUB), SS / TILE_S, BB);   // (16, 2, 64)
    ssp_mma<<<grid, 256, smem_bytes>>>(x, W, bias, sid, ccount, slen, out);
}